// round 9
// baseline (speedup 1.0000x reference)
#include <cuda_runtime.h>
#include <cuda_fp16.h>
#include <cstdint>

// Bilinear attention, B=16, T=D=1024:
//   qW = query @ W ; logits = qW @ keys^T + mask ; score = softmax(logits) ; ctx = score @ values
// GEMMs via mma.sync.m16n8k16 fp16, error-compensated split, fp32 accumulate.
// All operands PRE-SPLIT into f16 hi/lo planes in GMEM; GEMM producers are pure
// cp.async (no ALU, no STS). GEMM1 epilogue emits qW as hi/lo planes; softmax
// emits the f16 score plane for the 1-term GEMM3. Numerics identical to the
// producer-split version. 128 thr/CTA, warp tile 64x64, 3-stage k16 ring,
// one barrier per chunk.

#define NDIM 1024

// Static plane scratch (allocation-guard safe)
__device__ __half g_qh[16777216],  g_ql[16777216];    // query hi/lo
__device__ __half g_kh[16777216],  g_kl[16777216];    // keys hi/lo
__device__ __half g_qWh[16777216], g_qWl[16777216];   // qW hi/lo (GEMM1 out)
__device__ __half g_Wth[1048576],  g_Wtl[1048576];    // W^T hi/lo
__device__ __half g_valh[16777216];                   // values^T hi
__device__ __half g_sch[16777216];                    // score hi (softmax out)

// ---- helpers -------------------------------------------------------------
static __device__ __forceinline__ uint32_t smem_u32(const void* p) {
    uint32_t a;
    asm("{ .reg .u64 t; cvta.to.shared.u64 t, %1; cvt.u32.u64 %0, t; }" : "=r"(a) : "l"(p));
    return a;
}
static __device__ __forceinline__ uint32_t pack_h2(float e0, float e1) {
    uint32_t r;   // r.lo = f16(e0), r.hi = f16(e1)
    asm("cvt.rn.f16x2.f32 %0, %1, %2;" : "=r"(r) : "f"(e1), "f"(e0));
    return r;
}
static __device__ __forceinline__ void split_pair(float x, float y, uint32_t& h, uint32_t& l) {
    h = pack_h2(x, y);
    __half2 hh = *reinterpret_cast<__half2*>(&h);
    l = pack_h2(x - __low2float(hh), y - __high2float(hh));
}
static __device__ __forceinline__ void mma16(float* d, const uint32_t* a, const uint32_t* b) {
    asm volatile(
        "mma.sync.aligned.m16n8k16.row.col.f32.f16.f16.f32 "
        "{%0,%1,%2,%3}, {%4,%5,%6,%7}, {%8,%9}, {%0,%1,%2,%3};"
        : "+f"(d[0]), "+f"(d[1]), "+f"(d[2]), "+f"(d[3])
        : "r"(a[0]), "r"(a[1]), "r"(a[2]), "r"(a[3]), "r"(b[0]), "r"(b[1]));
}
static __device__ __forceinline__ void cpa16(uint32_t dst, const void* src) {
    asm volatile("cp.async.ca.shared.global [%0], [%1], 16;" :: "r"(dst), "l"(src));
}
static __device__ __forceinline__ void cp_commit() {
    asm volatile("cp.async.commit_group;" ::: "memory");
}

// SMEM plane row: 16 halves data + 8 halves pad = 48 B (conflict-free LDS).
#define ROWB 48
#define PLANE 6144

// TERMS==3: Ahi*Bhi + Ahi*Blo + Alo*Bhi ; TERMS==1: Ahi*Bhi
// EPI: 0 = f32 out, 1 = f32 + mask, 2 = f16 hi/lo plane out (qW)
template<int TERMS, int EPI>
__global__ __launch_bounds__(128) void gemm_plane_kernel(
    const __half* __restrict__ Ah, const __half* __restrict__ Al,
    const __half* __restrict__ Bh, const __half* __restrict__ Bl,
    float* __restrict__ C, __half* __restrict__ Ch, __half* __restrict__ Cl,
    const float* __restrict__ mask, size_t sA, size_t sB, size_t sC)
{
    constexpr int AHO = 0;
    constexpr int ALO = PLANE;
    constexpr int BHO = (TERMS == 3) ? 2 * PLANE : PLANE;
    constexpr int BLO = 3 * PLANE;
    constexpr int SLOT = (TERMS == 3) ? 4 * PLANE : 2 * PLANE;

    extern __shared__ __align__(16) char smem[];
    const uint32_t su = smem_u32(smem);
    const int tid = threadIdx.x, wid = tid >> 5, lid = tid & 31;
    const int g = lid >> 2, tg = lid & 3;                  // mma group / thread-in-group
    const int wm = (wid >> 1) * 64, wn = (wid & 1) * 64;   // 2x2 warp grid, 64x64 tiles
    const int M0 = blockIdx.y * 128, N0 = blockIdx.x * 128;
    const size_t b = blockIdx.z;
    Ah += b * sA + (size_t)M0 * NDIM;
    Bh += b * sB + (size_t)N0 * NDIM;
    if (TERMS == 3) {
        Al += b * sA + (size_t)M0 * NDIM;
        Bl += b * sB + (size_t)N0 * NDIM;
    }
    const float* mp = (EPI == 1) ? (mask + b * 1024) : nullptr;

    // producer: r2 = row (0..63, +64/pass), 16B piece h of the 32B k16 row slice
    const int r2 = tid >> 1;
    const int hb = (tid & 1) * 16;       // smem byte sub-offset
    const int hh = (tid & 1) * 8;        // gmem halves sub-offset

    float acc[4][8][4];
    #pragma unroll
    for (int mi = 0; mi < 4; mi++)
        #pragma unroll
        for (int ni = 0; ni < 8; ni++)
            #pragma unroll
            for (int v = 0; v < 4; v++) acc[mi][ni][v] = 0.0f;

    auto issue = [&](int c) {
        if (c < 64) {
            const uint32_t base = su + (c % 3) * SLOT;
            const int k0 = c << 4;
            #pragma unroll
            for (int p = 0; p < 2; p++) {
                const int row = r2 + 64 * p;
                const size_t go = (size_t)row * NDIM + k0 + hh;
                const uint32_t ro = row * ROWB + hb;
                cpa16(base + AHO + ro, Ah + go);
                cpa16(base + BHO + ro, Bh + go);
                if (TERMS == 3) {
                    cpa16(base + ALO + ro, Al + go);
                    cpa16(base + BLO + ro, Bl + go);
                }
            }
        }
        cp_commit();
    };

    auto frag_mma = [&](int slot) {
        const char* base = smem + slot * SLOT;
        uint32_t bh[8][2], bl[8][2];
        #pragma unroll
        for (int ni = 0; ni < 8; ni++) {
            const int n0 = (wn + ni * 8 + g) * ROWB + tg * 4;
            bh[ni][0] = *(const uint32_t*)(base + BHO + n0);
            bh[ni][1] = *(const uint32_t*)(base + BHO + n0 + 16);
            if (TERMS == 3) {
                bl[ni][0] = *(const uint32_t*)(base + BLO + n0);
                bl[ni][1] = *(const uint32_t*)(base + BLO + n0 + 16);
            }
        }
        #pragma unroll
        for (int mi = 0; mi < 4; mi++) {
            const int r0 = (wm + mi * 16 + g) * ROWB + tg * 4;
            const int r1 = r0 + 8 * ROWB;
            uint32_t ah[4], al[4];
            ah[0] = *(const uint32_t*)(base + AHO + r0);
            ah[1] = *(const uint32_t*)(base + AHO + r1);
            ah[2] = *(const uint32_t*)(base + AHO + r0 + 16);
            ah[3] = *(const uint32_t*)(base + AHO + r1 + 16);
            if (TERMS == 3) {
                al[0] = *(const uint32_t*)(base + ALO + r0);
                al[1] = *(const uint32_t*)(base + ALO + r1);
                al[2] = *(const uint32_t*)(base + ALO + r0 + 16);
                al[3] = *(const uint32_t*)(base + ALO + r1 + 16);
            }
            #pragma unroll
            for (int ni = 0; ni < 8; ni++) {
                mma16(acc[mi][ni], ah, bh[ni]);
                if (TERMS == 3) {
                    mma16(acc[mi][ni], ah, bl[ni]);
                    mma16(acc[mi][ni], al, bh[ni]);
                }
            }
        }
    };

    issue(0);
    issue(1);
    for (int c = 0; c < 64; c++) {
        asm volatile("cp.async.wait_group 1;" ::: "memory");
        __syncthreads();      // group c visible to all; prior slot reads done
        issue(c + 2);         // overwrites slot (c-1)%3 — drained before this bar
        frag_mma(c % 3);
    }

    // epilogue: d0,d1 at (g, 2tg..2tg+1), d2,d3 at (g+8, ...)
    #pragma unroll
    for (int mi = 0; mi < 4; mi++) {
        #pragma unroll
        for (int ni = 0; ni < 8; ni++) {
            const int r0 = M0 + wm + mi * 16 + g;
            const int cc = N0 + wn + ni * 8 + 2 * tg;
            float2 v0 = make_float2(acc[mi][ni][0], acc[mi][ni][1]);
            float2 v1 = make_float2(acc[mi][ni][2], acc[mi][ni][3]);
            if (EPI == 2) {
                uint32_t h0, l0, h1, l1;
                split_pair(v0.x, v0.y, h0, l0);
                split_pair(v1.x, v1.y, h1, l1);
                *(uint32_t*)(Ch + (size_t)r0 * NDIM + cc)       = h0;
                *(uint32_t*)(Cl + (size_t)r0 * NDIM + cc)       = l0;
                *(uint32_t*)(Ch + (size_t)(r0 + 8) * NDIM + cc) = h1;
                *(uint32_t*)(Cl + (size_t)(r0 + 8) * NDIM + cc) = l1;
            } else {
                if (EPI == 1) {
                    const float m0v = mp[cc], m1v = mp[cc + 1];
                    v0.x += m0v; v0.y += m1v;
                    v1.x += m0v; v1.y += m1v;
                }
                float* Cb = C + b * sC;
                *(float2*)(Cb + (size_t)r0 * NDIM + cc)       = v0;
                *(float2*)(Cb + (size_t)(r0 + 8) * NDIM + cc) = v1;
            }
        }
    }
}

// elementwise split: f32 -> f16 hi + f16 lo planes (float4 per thread)
__global__ __launch_bounds__(256) void split_kernel(const float4* __restrict__ src,
                                                    __half* __restrict__ dh,
                                                    __half* __restrict__ dl)
{
    const size_t i = (size_t)blockIdx.x * blockDim.x + threadIdx.x;
    float4 v = src[i];
    uint32_t h0, l0, h1, l1;
    split_pair(v.x, v.y, h0, l0);
    split_pair(v.z, v.w, h1, l1);
    *(uint2*)(dh + 4 * i) = make_uint2(h0, h1);
    *(uint2*)(dl + 4 * i) = make_uint2(l0, l1);
}

// 1024x1024 transpose + split to f16 planes (per blockIdx.z slice), block (32,8)
template<bool LO>
__global__ __launch_bounds__(256) void transpose_split_kernel(
    const float* __restrict__ src, __half* __restrict__ dh, __half* __restrict__ dl)
{
    __shared__ float t[32][33];
    const size_t b = blockIdx.z;
    src += b * 1048576ull;
    dh += b * 1048576ull;
    if (LO) dl += b * 1048576ull;
    const int bx = blockIdx.x * 32, by = blockIdx.y * 32;
    const int x = threadIdx.x, y4 = threadIdx.y * 4;
    #pragma unroll
    for (int i = 0; i < 4; i++)
        t[y4 + i][x] = src[(size_t)(by + y4 + i) * 1024 + bx + x];
    __syncthreads();
    #pragma unroll
    for (int i = 0; i < 4; i++) {
        const float v = t[x][y4 + i];
        const size_t o = (size_t)(bx + y4 + i) * 1024 + by + x;
        const __half h = __float2half_rn(v);
        dh[o] = h;
        if (LO) dl[o] = __float2half_rn(v - __half2float(h));
    }
}

// In-place row softmax, row length 1024; also emits f16 score plane
__global__ __launch_bounds__(256) void softmax_kernel(float* __restrict__ S,
                                                      __half* __restrict__ Sh)
{
    __shared__ float red[8];
    size_t row = blockIdx.x;
    float4* p = reinterpret_cast<float4*>(S + row * 1024);
    int t = threadIdx.x;

    float4 v = p[t];
    float m = fmaxf(fmaxf(v.x, v.y), fmaxf(v.z, v.w));
    #pragma unroll
    for (int o = 16; o; o >>= 1) m = fmaxf(m, __shfl_xor_sync(0xffffffffu, m, o));
    if ((t & 31) == 0) red[t >> 5] = m;
    __syncthreads();
    m = red[0];
    #pragma unroll
    for (int i = 1; i < 8; i++) m = fmaxf(m, red[i]);

    v.x = expf(v.x - m); v.y = expf(v.y - m);
    v.z = expf(v.z - m); v.w = expf(v.w - m);
    float s = v.x + v.y + v.z + v.w;
    #pragma unroll
    for (int o = 16; o; o >>= 1) s += __shfl_xor_sync(0xffffffffu, s, o);
    __syncthreads();
    if ((t & 31) == 0) red[t >> 5] = s;
    __syncthreads();
    s = red[0];
    #pragma unroll
    for (int i = 1; i < 8; i++) s += red[i];

    float inv = 1.0f / s;
    v.x *= inv; v.y *= inv; v.z *= inv; v.w *= inv;
    p[t] = v;

    uint32_t h0 = pack_h2(v.x, v.y), h1 = pack_h2(v.z, v.w);
    *(uint2*)(Sh + row * 1024 + 4 * t) = make_uint2(h0, h1);
}

extern "C" void kernel_launch(void* const* d_in, const int* in_sizes, int n_in,
                              void* d_out, int out_size)
{
    (void)in_sizes; (void)n_in; (void)out_size;
    const float* query  = (const float*)d_in[0];   // [16,1024,1024]
    const float* keys   = (const float*)d_in[1];   // [16,1024,1024]
    const float* values = (const float*)d_in[2];   // [16,1024,1024]
    const float* W      = (const float*)d_in[3];   // [1024,1024]
    const float* mask   = (const float*)d_in[4];   // [16,1024]

    float* score = (float*)d_out;                        // [16,1024,1024]
    float* ctx   = score + (size_t)16 * 1024 * 1024;     // [16,1024,1024]

    const int SMEM3 = 3 * 4 * PLANE;   // 73728
    const int SMEM1 = 3 * 2 * PLANE;   // 36864
    cudaFuncSetAttribute(gemm_plane_kernel<3, 2>,
                         cudaFuncAttributeMaxDynamicSharedMemorySize, SMEM3);
    cudaFuncSetAttribute(gemm_plane_kernel<3, 1>,
                         cudaFuncAttributeMaxDynamicSharedMemorySize, SMEM3);
    cudaFuncSetAttribute(gemm_plane_kernel<1, 0>,
                         cudaFuncAttributeMaxDynamicSharedMemorySize, SMEM1);

    __half *qh, *ql, *kh, *kl, *qWh, *qWl, *Wth, *Wtl, *valh, *sch;
    cudaGetSymbolAddress((void**)&qh,   g_qh);
    cudaGetSymbolAddress((void**)&ql,   g_ql);
    cudaGetSymbolAddress((void**)&kh,   g_kh);
    cudaGetSymbolAddress((void**)&kl,   g_kl);
    cudaGetSymbolAddress((void**)&qWh,  g_qWh);
    cudaGetSymbolAddress((void**)&qWl,  g_qWl);
    cudaGetSymbolAddress((void**)&Wth,  g_Wth);
    cudaGetSymbolAddress((void**)&Wtl,  g_Wtl);
    cudaGetSymbolAddress((void**)&valh, g_valh);
    cudaGetSymbolAddress((void**)&sch,  g_sch);

    // Pre-split all operands into f16 planes (bandwidth-bound, ~70 us total)
    split_kernel<<<16384, 256>>>((const float4*)query, qh, ql);
    split_kernel<<<16384, 256>>>((const float4*)keys,  kh, kl);
    transpose_split_kernel<true><<<dim3(32, 32, 1),  dim3(32, 8)>>>(W, Wth, Wtl);
    transpose_split_kernel<false><<<dim3(32, 32, 16), dim3(32, 8)>>>(values, valh, nullptr);

    // qW = query @ W  (NT, 3-term) -> qW hi/lo planes
    gemm_plane_kernel<3, 2><<<dim3(8, 128, 1), 128, SMEM3>>>(
        qh, ql, Wth, Wtl, nullptr, qWh, qWl, nullptr, 0, 0, 0);

    // logits = qW @ keys^T + mask -> score (f32, d_out)
    gemm_plane_kernel<3, 1><<<dim3(8, 8, 16), 128, SMEM3>>>(
        qWh, qWl, kh, kl, score, nullptr, nullptr, mask,
        1048576, 1048576, 1048576);

    // softmax in place; emit f16 score plane
    softmax_kernel<<<16384, 256>>>(score, sch);

    // ctx = score @ values (NT on values^T), 1-term fp16
    gemm_plane_kernel<1, 0><<<dim3(8, 8, 16), 128, SMEM1>>>(
        sch, nullptr, valh, nullptr, ctx, nullptr, nullptr, nullptr,
        1048576, 1048576, 1048576);
}

// round 10
// speedup vs baseline: 1.0436x; 1.0436x over previous
#include <cuda_runtime.h>
#include <cuda_fp16.h>
#include <cstdint>

// Bilinear attention, B=16, T=D=1024:
//   qW = query @ W ; logits = qW @ keys^T + mask ; score = softmax(logits) ; ctx = score @ values
// GEMMs via mma.sync.m16n8k16 fp16, error-compensated split, fp32 accumulate.
// WARP-SPECIALIZED: 256 threads/CTA = 4 producer warps (LDG -> split -> half2
// planes in SMEM, up to 3 chunks ahead) + 4 consumer warps (LDS+MMA only,
// 64x64 tiles). Named-barrier full/empty ring (3 slots). All GEMMs NT.
// TERMS: 3 = Ahi*Bhi+Ahi*Blo+Alo*Bhi (logit path) ; 1 = Ahi*Bhi (post-softmax)

#define NDIM 1024

// Static scratch (allocation-guard safe)
__device__ float g_qW[16777216];    // 16384 x 1024
__device__ float g_Wt[1048576];     // W^T
__device__ float g_valT[16777216];  // values^T per batch

// ---- helpers -------------------------------------------------------------
static __device__ __forceinline__ uint32_t pack_h2(float e0, float e1) {
    uint32_t r;   // r.lo = f16(e0), r.hi = f16(e1)
    asm("cvt.rn.f16x2.f32 %0, %1, %2;" : "=r"(r) : "f"(e1), "f"(e0));
    return r;
}
static __device__ __forceinline__ void split_pair(float x, float y, uint32_t& h, uint32_t& l) {
    h = pack_h2(x, y);
    __half2 hh = *reinterpret_cast<__half2*>(&h);
    l = pack_h2(x - __low2float(hh), y - __high2float(hh));
}
static __device__ __forceinline__ void mma16(float* d, const uint32_t* a, const uint32_t* b) {
    asm volatile(
        "mma.sync.aligned.m16n8k16.row.col.f32.f16.f16.f32 "
        "{%0,%1,%2,%3}, {%4,%5,%6,%7}, {%8,%9}, {%0,%1,%2,%3};"
        : "+f"(d[0]), "+f"(d[1]), "+f"(d[2]), "+f"(d[3])
        : "r"(a[0]), "r"(a[1]), "r"(a[2]), "r"(a[3]), "r"(b[0]), "r"(b[1]));
}
static __device__ __forceinline__ void bar_sync(int id) {
    asm volatile("bar.sync %0, 256;" :: "r"(id) : "memory");
}
static __device__ __forceinline__ void bar_arrive(int id) {
    asm volatile("bar.arrive %0, 256;" :: "r"(id) : "memory");
}

// ---- SMEM plane layout (as R8) --------------------------------------------
// Row = 16 halves data + 8 halves pad = 48 bytes (conflict-free frag LDS + STS).
// Planes per slot: A-hi, A-lo, B-hi, B-lo, each 128 rows x 48B = 6144 B. 3 slots.
#define ROWB 48
#define AH_OFF 0
#define AL_OFF 6144
#define BH_OFF 12288
#define BL_OFF 18432
#define SLOT_BYTES 24576
static constexpr int SMEM_BYTES = 3 * SLOT_BYTES;   // 73728

template<bool ADDMASK, int TERMS>
__global__ __launch_bounds__(256, 1) void gemm_ws_kernel(
    const float* __restrict__ A, const float* __restrict__ B,
    float* __restrict__ C, const float* __restrict__ mask,
    size_t sA, size_t sB, size_t sC)
{
    extern __shared__ __align__(16) char smem[];
    const int tid = threadIdx.x;
    const int M0 = blockIdx.y * 128, N0 = blockIdx.x * 128;
    const size_t b = blockIdx.z;
    A += b * sA; B += b * sB; C += b * sC;

    if (tid >= 128) {
        // ---------------- producer warps (4..7) ----------------
        const int pid = tid - 128;
        const int r = pid >> 2, q = pid & 3;
        const float* Ag = A + (size_t)(M0 + r) * NDIM + 4 * q;
        const float* Bg = B + (size_t)(N0 + r) * NDIM + 4 * q;
        float4 bufA[4], bufB[4];

        for (int c = 0; c < 64; c++) {
            const int k0 = c << 4;
            #pragma unroll
            for (int p = 0; p < 4; p++) {
                bufA[p] = *(const float4*)(Ag + (size_t)32 * p * NDIM + k0);
                bufB[p] = *(const float4*)(Bg + (size_t)32 * p * NDIM + k0);
            }
            const int s = c % 3;
            if (c >= 3) bar_sync(4 + s);      // wait slot drained (LDG in flight meanwhile)
            char* base = smem + s * SLOT_BYTES;
            #pragma unroll
            for (int p = 0; p < 4; p++) {
                const int ro = (r + 32 * p) * ROWB + q * 8;
                uint32_t h0, h1, l0, l1;
                if (TERMS >= 2) {
                    split_pair(bufA[p].x, bufA[p].y, h0, l0);
                    split_pair(bufA[p].z, bufA[p].w, h1, l1);
                    *(uint2*)(base + AH_OFF + ro) = make_uint2(h0, h1);
                    *(uint2*)(base + AL_OFF + ro) = make_uint2(l0, l1);
                } else {
                    h0 = pack_h2(bufA[p].x, bufA[p].y);
                    h1 = pack_h2(bufA[p].z, bufA[p].w);
                    *(uint2*)(base + AH_OFF + ro) = make_uint2(h0, h1);
                }
                if (TERMS == 3) {
                    split_pair(bufB[p].x, bufB[p].y, h0, l0);
                    split_pair(bufB[p].z, bufB[p].w, h1, l1);
                    *(uint2*)(base + BH_OFF + ro) = make_uint2(h0, h1);
                    *(uint2*)(base + BL_OFF + ro) = make_uint2(l0, l1);
                } else {
                    h0 = pack_h2(bufB[p].x, bufB[p].y);
                    h1 = pack_h2(bufB[p].z, bufB[p].w);
                    *(uint2*)(base + BH_OFF + ro) = make_uint2(h0, h1);
                }
            }
            bar_arrive(1 + s);                // slot full
        }
        return;                               // producers exit; no one waits on them
    }

    // ---------------- consumer warps (0..3) ----------------
    const int wid = tid >> 5, lid = tid & 31;
    const int g = lid >> 2, tg = lid & 3;
    const int wm = (wid >> 1) * 64, wn = (wid & 1) * 64;   // 2x2 warp grid, 64x64 tiles
    const float* mp = ADDMASK ? (mask + b * 1024) : nullptr;

    float acc[4][8][4];
    #pragma unroll
    for (int mi = 0; mi < 4; mi++)
        #pragma unroll
        for (int ni = 0; ni < 8; ni++)
            #pragma unroll
            for (int v = 0; v < 4; v++) acc[mi][ni][v] = 0.0f;

    for (int c = 0; c < 64; c++) {
        const int s = c % 3;
        bar_sync(1 + s);                      // wait slot full
        const char* base = smem + s * SLOT_BYTES;

        uint32_t bh[8][2], bl[8][2];
        #pragma unroll
        for (int ni = 0; ni < 8; ni++) {
            const int n0 = (wn + ni * 8 + g) * ROWB + tg * 4;
            bh[ni][0] = *(const uint32_t*)(base + BH_OFF + n0);
            bh[ni][1] = *(const uint32_t*)(base + BH_OFF + n0 + 16);
            if (TERMS == 3) {
                bl[ni][0] = *(const uint32_t*)(base + BL_OFF + n0);
                bl[ni][1] = *(const uint32_t*)(base + BL_OFF + n0 + 16);
            }
        }
        #pragma unroll
        for (int mi = 0; mi < 4; mi++) {
            const int r0 = (wm + mi * 16 + g) * ROWB + tg * 4;
            const int r1 = r0 + 8 * ROWB;
            uint32_t ah[4], al[4];
            ah[0] = *(const uint32_t*)(base + AH_OFF + r0);
            ah[1] = *(const uint32_t*)(base + AH_OFF + r1);
            ah[2] = *(const uint32_t*)(base + AH_OFF + r0 + 16);
            ah[3] = *(const uint32_t*)(base + AH_OFF + r1 + 16);
            if (TERMS >= 2) {
                al[0] = *(const uint32_t*)(base + AL_OFF + r0);
                al[1] = *(const uint32_t*)(base + AL_OFF + r1);
                al[2] = *(const uint32_t*)(base + AL_OFF + r0 + 16);
                al[3] = *(const uint32_t*)(base + AL_OFF + r1 + 16);
            }
            #pragma unroll
            for (int ni = 0; ni < 8; ni++) {
                mma16(acc[mi][ni], ah, bh[ni]);
                if (TERMS == 3) mma16(acc[mi][ni], ah, bl[ni]);
                if (TERMS >= 2) mma16(acc[mi][ni], al, bh[ni]);
            }
        }
        bar_arrive(4 + s);                    // slot empty
    }

    // epilogue (consumers only): d0,d1 at (g, 2tg..2tg+1), d2,d3 at (g+8, ...)
    #pragma unroll
    for (int mi = 0; mi < 4; mi++) {
        #pragma unroll
        for (int ni = 0; ni < 8; ni++) {
            const int r0 = M0 + wm + mi * 16 + g;
            const int cc = N0 + wn + ni * 8 + 2 * tg;
            float2 v0 = make_float2(acc[mi][ni][0], acc[mi][ni][1]);
            float2 v1 = make_float2(acc[mi][ni][2], acc[mi][ni][3]);
            if (ADDMASK) {
                const float m0v = mp[cc], m1v = mp[cc + 1];
                v0.x += m0v; v0.y += m1v;
                v1.x += m0v; v1.y += m1v;
            }
            *(float2*)(C + (size_t)r0 * NDIM + cc)       = v0;
            *(float2*)(C + (size_t)(r0 + 8) * NDIM + cc) = v1;
        }
    }
}

// 1024x1024 f32 transpose (per blockIdx.z slice), block (32,8)
__global__ __launch_bounds__(256) void transpose_kernel(const float* __restrict__ src,
                                                        float* __restrict__ dst)
{
    __shared__ float t[32][33];
    const size_t b = blockIdx.z;
    src += b * 1048576ull; dst += b * 1048576ull;
    const int bx = blockIdx.x * 32, by = blockIdx.y * 32;
    const int x = threadIdx.x, y4 = threadIdx.y * 4;
    #pragma unroll
    for (int i = 0; i < 4; i++)
        t[y4 + i][x] = src[(size_t)(by + y4 + i) * 1024 + bx + x];
    __syncthreads();
    #pragma unroll
    for (int i = 0; i < 4; i++)
        dst[(size_t)(bx + y4 + i) * 1024 + by + x] = t[x][y4 + i];
}

// In-place row softmax, row length 1024
__global__ __launch_bounds__(256) void softmax_kernel(float* __restrict__ S)
{
    __shared__ float red[8];
    size_t row = blockIdx.x;
    float4* p = reinterpret_cast<float4*>(S + row * 1024);
    int t = threadIdx.x;

    float4 v = p[t];
    float m = fmaxf(fmaxf(v.x, v.y), fmaxf(v.z, v.w));
    #pragma unroll
    for (int o = 16; o; o >>= 1) m = fmaxf(m, __shfl_xor_sync(0xffffffffu, m, o));
    if ((t & 31) == 0) red[t >> 5] = m;
    __syncthreads();
    m = red[0];
    #pragma unroll
    for (int i = 1; i < 8; i++) m = fmaxf(m, red[i]);

    v.x = expf(v.x - m); v.y = expf(v.y - m);
    v.z = expf(v.z - m); v.w = expf(v.w - m);
    float s = v.x + v.y + v.z + v.w;
    #pragma unroll
    for (int o = 16; o; o >>= 1) s += __shfl_xor_sync(0xffffffffu, s, o);
    __syncthreads();
    if ((t & 31) == 0) red[t >> 5] = s;
    __syncthreads();
    s = red[0];
    #pragma unroll
    for (int i = 1; i < 8; i++) s += red[i];

    float inv = 1.0f / s;
    v.x *= inv; v.y *= inv; v.z *= inv; v.w *= inv;
    p[t] = v;
}

extern "C" void kernel_launch(void* const* d_in, const int* in_sizes, int n_in,
                              void* d_out, int out_size)
{
    (void)in_sizes; (void)n_in; (void)out_size;
    const float* query  = (const float*)d_in[0];   // [16,1024,1024]
    const float* keys   = (const float*)d_in[1];   // [16,1024,1024]
    const float* values = (const float*)d_in[2];   // [16,1024,1024]
    const float* W      = (const float*)d_in[3];   // [1024,1024]
    const float* mask   = (const float*)d_in[4];   // [16,1024]

    float* score = (float*)d_out;                        // [16,1024,1024]
    float* ctx   = score + (size_t)16 * 1024 * 1024;     // [16,1024,1024]

    cudaFuncSetAttribute(gemm_ws_kernel<false, 3>,
                         cudaFuncAttributeMaxDynamicSharedMemorySize, SMEM_BYTES);
    cudaFuncSetAttribute(gemm_ws_kernel<true, 3>,
                         cudaFuncAttributeMaxDynamicSharedMemorySize, SMEM_BYTES);
    cudaFuncSetAttribute(gemm_ws_kernel<false, 1>,
                         cudaFuncAttributeMaxDynamicSharedMemorySize, SMEM_BYTES);

    float* qW;   cudaGetSymbolAddress((void**)&qW,   g_qW);
    float* Wt;   cudaGetSymbolAddress((void**)&Wt,   g_Wt);
    float* valT; cudaGetSymbolAddress((void**)&valT, g_valT);

    // Prep: W^T and values^T so every GEMM is NT (B consumed [N,K] row-major)
    transpose_kernel<<<dim3(32, 32, 1),  dim3(32, 8)>>>(W, Wt);
    transpose_kernel<<<dim3(32, 32, 16), dim3(32, 8)>>>(values, valT);

    // qW = query @ W : one 16384x1024x1024 NT GEMM (W batch-shared), 3-term
    gemm_ws_kernel<false, 3><<<dim3(8, 128, 1), 256, SMEM_BYTES>>>(
        query, Wt, qW, nullptr, 0, 0, 0);

    // logits = qW @ keys^T + mask -> score (NT), 3-term (softmax amplifies logit error)
    gemm_ws_kernel<true, 3><<<dim3(8, 8, 16), 256, SMEM_BYTES>>>(
        qW, keys, score, mask, 1048576, 1048576, 1048576);

    // softmax in place over last dim
    softmax_kernel<<<16384, 256>>>(score);

    // ctx = score @ values (NT on values^T), 1-term pure fp16 (~2.4e-4 rel total)
    gemm_ws_kernel<false, 1><<<dim3(8, 8, 16), 256, SMEM_BYTES>>>(
        score, valT, ctx, nullptr, 1048576, 1048576, 1048576);
}